// round 15
// baseline (speedup 1.0000x reference)
#include <cuda_runtime.h>
#include <cuda_bf16.h>

// Problem shape (fixed by the dataset): [B=32, C=1, H=1024, W=1024] fp32.
#define B_DIM 32
#define HW (1024 * 1024)
#define HW4 (HW / 4)            // 262144 float4 pixels
#define TPB 128
#define PPT 8                   // pixel4's per thread
#define GRID (HW4 / (TPB * PPT))  // 256 blocks, 2 blocks/SM reg-limited
#define LAMBDA 0.1

// Global accumulators: [0]=diff2, [1]=G2, [2]=H2. Zero at module load; the
// last block of each launch resets them, so every graph replay starts clean.
__device__ double g_acc[3];
__device__ unsigned int g_count;

__global__ __launch_bounds__(TPB, 2) void praloss_fused_kernel(
    const float4* __restrict__ est, const float4* __restrict__ gt,
    float* __restrict__ out)
{
    // Block-contiguous layout: this block owns float4 indices
    // [blockIdx*TPB*PPT, (blockIdx+1)*TPB*PPT); thread t handles
    // base+t+p*TPB for p in 0..7. Per batch per tensor the block reads one
    // contiguous 16KB extent (DRAM row locality), and each thread keeps
    // 16 independent LDG.128 in flight per batch step (MLP ~32 with
    // cross-iteration overlap).
    const int base = blockIdx.x * (TPB * PPT) + threadIdx.x;

    // Per-pixel accumulators: sum(e-g) and sum(e^2) per pixel;
    // sum((e-g)^2) merged across pixels (diff2 needs no per-pixel mask).
    float4 sd[PPT], qe[PPT];
    float4 qd = make_float4(0.f, 0.f, 0.f, 0.f);
    #pragma unroll
    for (int p = 0; p < PPT; p++) { sd[p] = qd; qe[p] = qd; }

    const float4* pe = est + base;
    const float4* pg = gt  + base;

    for (int b = 0; b < B_DIM; b++) {
        const long off = (long)b * HW4;
        float4 e[PPT], g[PPT];
        // Batch all 16 loads first — independent, front-loaded MLP.
        #pragma unroll
        for (int p = 0; p < PPT; p++) {
            e[p] = pe[off + p * TPB];
            g[p] = pg[off + p * TPB];
        }
        #pragma unroll
        for (int p = 0; p < PPT; p++) {
            float dx = e[p].x - g[p].x, dy = e[p].y - g[p].y;
            float dz = e[p].z - g[p].z, dw = e[p].w - g[p].w;
            sd[p].x += dx; sd[p].y += dy; sd[p].z += dz; sd[p].w += dw;
            qd.x = fmaf(dx, dx, qd.x); qd.y = fmaf(dy, dy, qd.y);
            qd.z = fmaf(dz, dz, qd.z); qd.w = fmaf(dw, dw, qd.w);
            qe[p].x = fmaf(e[p].x, e[p].x, qe[p].x);
            qe[p].y = fmaf(e[p].y, e[p].y, qe[p].y);
            qe[p].z = fmaf(e[p].z, e[p].z, qe[p].z);
            qe[p].w = fmaf(e[p].w, e[p].w, qe[p].w);
        }
    }

    float diff2 = (qd.x + qd.y) + (qd.z + qd.w);
    float G2 = 0.f, H2 = 0.f;
    // mask: sum(est) > sum(gt) <=> sum(est-gt) > 0 (up to fp rounding)
    #pragma unroll
    for (int p = 0; p < PPT; p++) {
        G2 += (qe[p].x + qe[p].y) + (qe[p].z + qe[p].w);
        H2 += (sd[p].x > 0.f ? qe[p].x : 0.f)
            + (sd[p].y > 0.f ? qe[p].y : 0.f)
            + (sd[p].z > 0.f ? qe[p].z : 0.f)
            + (sd[p].w > 0.f ? qe[p].w : 0.f);
    }

    // Warp reduce (3 scalars)
    #pragma unroll
    for (int off = 16; off > 0; off >>= 1) {
        diff2 += __shfl_down_sync(0xFFFFFFFFu, diff2, off);
        G2    += __shfl_down_sync(0xFFFFFFFFu, G2,    off);
        H2    += __shfl_down_sync(0xFFFFFFFFu, H2,    off);
    }

    // Block reduce via shared memory (4 warps per 128-thread block)
    __shared__ float sm[3][4];
    const int lane = threadIdx.x & 31;
    const int wid  = threadIdx.x >> 5;
    if (lane == 0) {
        sm[0][wid] = diff2; sm[1][wid] = G2; sm[2][wid] = H2;
    }
    __syncthreads();

    if (threadIdx.x == 0) {
        float v0 = 0.f, v1 = 0.f, v2 = 0.f;
        #pragma unroll
        for (int w = 0; w < 4; w++) {
            v0 += sm[0][w]; v1 += sm[1][w]; v2 += sm[2][w];
        }
        atomicAdd(&g_acc[0], (double)v0);
        atomicAdd(&g_acc[1], (double)v1);
        atomicAdd(&g_acc[2], (double)v2);

        // Order this block's accumulator atomics before the ticket.
        __threadfence();
        unsigned int old = atomicAdd(&g_count, 1u);
        if (old == (unsigned int)(GRID - 1)) {
            // Last block: all accumulator atomics are L2-visible.
            double diff2d = *((volatile double*)&g_acc[0]);
            double G2d    = *((volatile double*)&g_acc[1]);
            double H2d    = *((volatile double*)&g_acc[2]);
            out[0] = (float)(diff2d / G2d + LAMBDA * (diff2d / H2d));
            // Reset state for the next graph replay; no other thread-0 is
            // still touching these, and stream order protects later launches.
            *((volatile double*)&g_acc[0]) = 0.0;
            *((volatile double*)&g_acc[1]) = 0.0;
            *((volatile double*)&g_acc[2]) = 0.0;
            __threadfence();
            atomicExch(&g_count, 0u);
        }
    }
}

extern "C" void kernel_launch(void* const* d_in, const int* in_sizes, int n_in,
                              void* d_out, int out_size) {
    const float4* est = (const float4*)d_in[0];
    const float4* gt  = (const float4*)d_in[1];
    float* out = (float*)d_out;

    praloss_fused_kernel<<<GRID, TPB>>>(est, gt, out);
}

// round 16
// speedup vs baseline: 1.0618x; 1.0618x over previous
#include <cuda_runtime.h>
#include <cuda_bf16.h>

// Problem shape (fixed by the dataset): [B=32, C=1, H=1024, W=1024] fp32.
#define B_DIM 32
#define HW (1024 * 1024)
#define HW4 (HW / 4)            // 262144 float4 pixels
#define TPB 128
#define PPT 4                   // pixel4's per thread (measured optimum)
#define GRID (HW4 / (TPB * PPT))  // 512 blocks -> single wave at 4 blocks/SM
#define LAMBDA 0.1

// Global accumulators: [0]=diff2, [1]=G2, [2]=H2. Zero at module load; the
// last block of each launch resets them, so every graph replay starts clean.
__device__ double g_acc[3];
__device__ unsigned int g_count;

__global__ __launch_bounds__(TPB, 4) void praloss_fused_kernel(
    const float4* __restrict__ est, const float4* __restrict__ gt,
    float* __restrict__ out)
{
    // Block-contiguous layout: this block owns float4 indices
    // [blockIdx*TPB*PPT, (blockIdx+1)*TPB*PPT); thread t handles
    // base+t, base+t+TPB, base+t+2*TPB, base+t+3*TPB. Per batch per tensor
    // the block reads one contiguous 8KB extent (DRAM row locality — the
    // measured optimum; 2KB, 4KB, and 16KB extents all measured worse).
    const int base = blockIdx.x * (TPB * PPT) + threadIdx.x;

    // Per-pixel accumulators (4 pixel4's): sum(e-g) and sum(e^2) per pixel;
    // sum((e-g)^2) merged across pixels (diff2 needs no per-pixel mask).
    float4 sd0 = make_float4(0.f,0.f,0.f,0.f), sd1 = sd0, sd2 = sd0, sd3 = sd0;
    float4 qe0 = sd0, qe1 = sd0, qe2 = sd0, qe3 = sd0;
    float4 qd  = sd0;

    const float4* pe = est + base;
    const float4* pg = gt  + base;

    #pragma unroll 2
    for (int b = 0; b < B_DIM; b++) {
        const long off = (long)b * HW4;
        const float4 e0 = pe[off];
        const float4 g0 = pg[off];
        const float4 e1 = pe[off + TPB];
        const float4 g1 = pg[off + TPB];
        const float4 e2 = pe[off + 2 * TPB];
        const float4 g2 = pg[off + 2 * TPB];
        const float4 e3 = pe[off + 3 * TPB];
        const float4 g3 = pg[off + 3 * TPB];

        float dx, dy, dz, dw;

        dx = e0.x - g0.x; dy = e0.y - g0.y; dz = e0.z - g0.z; dw = e0.w - g0.w;
        sd0.x += dx; sd0.y += dy; sd0.z += dz; sd0.w += dw;
        qd.x = fmaf(dx, dx, qd.x); qd.y = fmaf(dy, dy, qd.y);
        qd.z = fmaf(dz, dz, qd.z); qd.w = fmaf(dw, dw, qd.w);
        qe0.x = fmaf(e0.x, e0.x, qe0.x); qe0.y = fmaf(e0.y, e0.y, qe0.y);
        qe0.z = fmaf(e0.z, e0.z, qe0.z); qe0.w = fmaf(e0.w, e0.w, qe0.w);

        dx = e1.x - g1.x; dy = e1.y - g1.y; dz = e1.z - g1.z; dw = e1.w - g1.w;
        sd1.x += dx; sd1.y += dy; sd1.z += dz; sd1.w += dw;
        qd.x = fmaf(dx, dx, qd.x); qd.y = fmaf(dy, dy, qd.y);
        qd.z = fmaf(dz, dz, qd.z); qd.w = fmaf(dw, dw, qd.w);
        qe1.x = fmaf(e1.x, e1.x, qe1.x); qe1.y = fmaf(e1.y, e1.y, qe1.y);
        qe1.z = fmaf(e1.z, e1.z, qe1.z); qe1.w = fmaf(e1.w, e1.w, qe1.w);

        dx = e2.x - g2.x; dy = e2.y - g2.y; dz = e2.z - g2.z; dw = e2.w - g2.w;
        sd2.x += dx; sd2.y += dy; sd2.z += dz; sd2.w += dw;
        qd.x = fmaf(dx, dx, qd.x); qd.y = fmaf(dy, dy, qd.y);
        qd.z = fmaf(dz, dz, qd.z); qd.w = fmaf(dw, dw, qd.w);
        qe2.x = fmaf(e2.x, e2.x, qe2.x); qe2.y = fmaf(e2.y, e2.y, qe2.y);
        qe2.z = fmaf(e2.z, e2.z, qe2.z); qe2.w = fmaf(e2.w, e2.w, qe2.w);

        dx = e3.x - g3.x; dy = e3.y - g3.y; dz = e3.z - g3.z; dw = e3.w - g3.w;
        sd3.x += dx; sd3.y += dy; sd3.z += dz; sd3.w += dw;
        qd.x = fmaf(dx, dx, qd.x); qd.y = fmaf(dy, dy, qd.y);
        qd.z = fmaf(dz, dz, qd.z); qd.w = fmaf(dw, dw, qd.w);
        qe3.x = fmaf(e3.x, e3.x, qe3.x); qe3.y = fmaf(e3.y, e3.y, qe3.y);
        qe3.z = fmaf(e3.z, e3.z, qe3.z); qe3.w = fmaf(e3.w, e3.w, qe3.w);
    }

    float diff2 = (qd.x + qd.y) + (qd.z + qd.w);
    float G2 = (qe0.x + qe0.y) + (qe0.z + qe0.w)
             + (qe1.x + qe1.y) + (qe1.z + qe1.w)
             + (qe2.x + qe2.y) + (qe2.z + qe2.w)
             + (qe3.x + qe3.y) + (qe3.z + qe3.w);
    // mask: sum(est) > sum(gt) <=> sum(est-gt) > 0 (up to fp rounding)
    float H2 = (sd0.x > 0.f ? qe0.x : 0.f) + (sd0.y > 0.f ? qe0.y : 0.f)
             + (sd0.z > 0.f ? qe0.z : 0.f) + (sd0.w > 0.f ? qe0.w : 0.f)
             + (sd1.x > 0.f ? qe1.x : 0.f) + (sd1.y > 0.f ? qe1.y : 0.f)
             + (sd1.z > 0.f ? qe1.z : 0.f) + (sd1.w > 0.f ? qe1.w : 0.f)
             + (sd2.x > 0.f ? qe2.x : 0.f) + (sd2.y > 0.f ? qe2.y : 0.f)
             + (sd2.z > 0.f ? qe2.z : 0.f) + (sd2.w > 0.f ? qe2.w : 0.f)
             + (sd3.x > 0.f ? qe3.x : 0.f) + (sd3.y > 0.f ? qe3.y : 0.f)
             + (sd3.z > 0.f ? qe3.z : 0.f) + (sd3.w > 0.f ? qe3.w : 0.f);

    // Warp reduce (3 scalars)
    #pragma unroll
    for (int off = 16; off > 0; off >>= 1) {
        diff2 += __shfl_down_sync(0xFFFFFFFFu, diff2, off);
        G2    += __shfl_down_sync(0xFFFFFFFFu, G2,    off);
        H2    += __shfl_down_sync(0xFFFFFFFFu, H2,    off);
    }

    // Block reduce via shared memory (4 warps per 128-thread block)
    __shared__ float sm[3][4];
    const int lane = threadIdx.x & 31;
    const int wid  = threadIdx.x >> 5;
    if (lane == 0) {
        sm[0][wid] = diff2; sm[1][wid] = G2; sm[2][wid] = H2;
    }
    __syncthreads();

    if (threadIdx.x == 0) {
        float v0 = 0.f, v1 = 0.f, v2 = 0.f;
        #pragma unroll
        for (int w = 0; w < 4; w++) {
            v0 += sm[0][w]; v1 += sm[1][w]; v2 += sm[2][w];
        }
        atomicAdd(&g_acc[0], (double)v0);
        atomicAdd(&g_acc[1], (double)v1);
        atomicAdd(&g_acc[2], (double)v2);

        // Order this block's accumulator atomics before the ticket.
        __threadfence();
        unsigned int old = atomicAdd(&g_count, 1u);
        if (old == (unsigned int)(GRID - 1)) {
            // Last block: all accumulator atomics are L2-visible.
            double diff2d = *((volatile double*)&g_acc[0]);
            double G2d    = *((volatile double*)&g_acc[1]);
            double H2d    = *((volatile double*)&g_acc[2]);
            out[0] = (float)(diff2d / G2d + LAMBDA * (diff2d / H2d));
            // Reset state for the next graph replay; no other thread-0 is
            // still touching these, and stream order protects later launches.
            *((volatile double*)&g_acc[0]) = 0.0;
            *((volatile double*)&g_acc[1]) = 0.0;
            *((volatile double*)&g_acc[2]) = 0.0;
            __threadfence();
            atomicExch(&g_count, 0u);
        }
    }
}

extern "C" void kernel_launch(void* const* d_in, const int* in_sizes, int n_in,
                              void* d_out, int out_size) {
    const float4* est = (const float4*)d_in[0];
    const float4* gt  = (const float4*)d_in[1];
    float* out = (float*)d_out;

    praloss_fused_kernel<<<GRID, TPB>>>(est, gt, out);
}

// round 17
// speedup vs baseline: 1.0936x; 1.0300x over previous
#include <cuda_runtime.h>
#include <cuda_bf16.h>

// Problem shape (fixed by the dataset): [B=32, C=1, H=1024, W=1024] fp32.
//
// FINAL KERNEL — measured optimum after a 16-round sweep:
//   - single-pass: per-pixel batch-sum sign (mask), sum(e^2), sum((e-g)^2)
//     computed in one read of each tensor (256 MB total, no intermediates)
//   - TPB=128, PPT=4, block-contiguous 8KB extents, unroll-2 (~16 LDG.128
//     in flight/thread, regs 114), 512 blocks = 1 wave at 4 blocks/SM
//   - fused last-block finalize (out[0]) + state reset for graph replay
// Achieves ~6.26 TB/s (78% of HBM spec) — the measured efficiency plateau;
// all perturbations (PPT 2/8, TPB 64/256, grids 256-1024, .CS loads,
// strided layouts, 3-kernel graph) measured equal or worse.
#define B_DIM 32
#define HW (1024 * 1024)
#define HW4 (HW / 4)            // 262144 float4 pixels
#define TPB 128
#define PPT 4                   // pixel4's per thread (measured optimum)
#define GRID (HW4 / (TPB * PPT))  // 512 blocks -> single wave at 4 blocks/SM
#define LAMBDA 0.1

// Global accumulators: [0]=diff2, [1]=G2, [2]=H2. Zero at module load; the
// last block of each launch resets them, so every graph replay starts clean.
__device__ double g_acc[3];
__device__ unsigned int g_count;

__global__ __launch_bounds__(TPB, 4) void praloss_fused_kernel(
    const float4* __restrict__ est, const float4* __restrict__ gt,
    float* __restrict__ out)
{
    // Block-contiguous layout: this block owns float4 indices
    // [blockIdx*TPB*PPT, (blockIdx+1)*TPB*PPT); thread t handles
    // base+t, base+t+TPB, base+t+2*TPB, base+t+3*TPB.
    const int base = blockIdx.x * (TPB * PPT) + threadIdx.x;

    // Per-pixel accumulators (4 pixel4's): sum(e-g) and sum(e^2) per pixel;
    // sum((e-g)^2) merged across pixels (diff2 needs no per-pixel mask).
    float4 sd0 = make_float4(0.f,0.f,0.f,0.f), sd1 = sd0, sd2 = sd0, sd3 = sd0;
    float4 qe0 = sd0, qe1 = sd0, qe2 = sd0, qe3 = sd0;
    float4 qd  = sd0;

    const float4* pe = est + base;
    const float4* pg = gt  + base;

    #pragma unroll 2
    for (int b = 0; b < B_DIM; b++) {
        const long off = (long)b * HW4;
        const float4 e0 = pe[off];
        const float4 g0 = pg[off];
        const float4 e1 = pe[off + TPB];
        const float4 g1 = pg[off + TPB];
        const float4 e2 = pe[off + 2 * TPB];
        const float4 g2 = pg[off + 2 * TPB];
        const float4 e3 = pe[off + 3 * TPB];
        const float4 g3 = pg[off + 3 * TPB];

        float dx, dy, dz, dw;

        dx = e0.x - g0.x; dy = e0.y - g0.y; dz = e0.z - g0.z; dw = e0.w - g0.w;
        sd0.x += dx; sd0.y += dy; sd0.z += dz; sd0.w += dw;
        qd.x = fmaf(dx, dx, qd.x); qd.y = fmaf(dy, dy, qd.y);
        qd.z = fmaf(dz, dz, qd.z); qd.w = fmaf(dw, dw, qd.w);
        qe0.x = fmaf(e0.x, e0.x, qe0.x); qe0.y = fmaf(e0.y, e0.y, qe0.y);
        qe0.z = fmaf(e0.z, e0.z, qe0.z); qe0.w = fmaf(e0.w, e0.w, qe0.w);

        dx = e1.x - g1.x; dy = e1.y - g1.y; dz = e1.z - g1.z; dw = e1.w - g1.w;
        sd1.x += dx; sd1.y += dy; sd1.z += dz; sd1.w += dw;
        qd.x = fmaf(dx, dx, qd.x); qd.y = fmaf(dy, dy, qd.y);
        qd.z = fmaf(dz, dz, qd.z); qd.w = fmaf(dw, dw, qd.w);
        qe1.x = fmaf(e1.x, e1.x, qe1.x); qe1.y = fmaf(e1.y, e1.y, qe1.y);
        qe1.z = fmaf(e1.z, e1.z, qe1.z); qe1.w = fmaf(e1.w, e1.w, qe1.w);

        dx = e2.x - g2.x; dy = e2.y - g2.y; dz = e2.z - g2.z; dw = e2.w - g2.w;
        sd2.x += dx; sd2.y += dy; sd2.z += dz; sd2.w += dw;
        qd.x = fmaf(dx, dx, qd.x); qd.y = fmaf(dy, dy, qd.y);
        qd.z = fmaf(dz, dz, qd.z); qd.w = fmaf(dw, dw, qd.w);
        qe2.x = fmaf(e2.x, e2.x, qe2.x); qe2.y = fmaf(e2.y, e2.y, qe2.y);
        qe2.z = fmaf(e2.z, e2.z, qe2.z); qe2.w = fmaf(e2.w, e2.w, qe2.w);

        dx = e3.x - g3.x; dy = e3.y - g3.y; dz = e3.z - g3.z; dw = e3.w - g3.w;
        sd3.x += dx; sd3.y += dy; sd3.z += dz; sd3.w += dw;
        qd.x = fmaf(dx, dx, qd.x); qd.y = fmaf(dy, dy, qd.y);
        qd.z = fmaf(dz, dz, qd.z); qd.w = fmaf(dw, dw, qd.w);
        qe3.x = fmaf(e3.x, e3.x, qe3.x); qe3.y = fmaf(e3.y, e3.y, qe3.y);
        qe3.z = fmaf(e3.z, e3.z, qe3.z); qe3.w = fmaf(e3.w, e3.w, qe3.w);
    }

    float diff2 = (qd.x + qd.y) + (qd.z + qd.w);
    float G2 = (qe0.x + qe0.y) + (qe0.z + qe0.w)
             + (qe1.x + qe1.y) + (qe1.z + qe1.w)
             + (qe2.x + qe2.y) + (qe2.z + qe2.w)
             + (qe3.x + qe3.y) + (qe3.z + qe3.w);
    // mask: sum(est) > sum(gt) <=> sum(est-gt) > 0 (up to fp rounding)
    float H2 = (sd0.x > 0.f ? qe0.x : 0.f) + (sd0.y > 0.f ? qe0.y : 0.f)
             + (sd0.z > 0.f ? qe0.z : 0.f) + (sd0.w > 0.f ? qe0.w : 0.f)
             + (sd1.x > 0.f ? qe1.x : 0.f) + (sd1.y > 0.f ? qe1.y : 0.f)
             + (sd1.z > 0.f ? qe1.z : 0.f) + (sd1.w > 0.f ? qe1.w : 0.f)
             + (sd2.x > 0.f ? qe2.x : 0.f) + (sd2.y > 0.f ? qe2.y : 0.f)
             + (sd2.z > 0.f ? qe2.z : 0.f) + (sd2.w > 0.f ? qe2.w : 0.f)
             + (sd3.x > 0.f ? qe3.x : 0.f) + (sd3.y > 0.f ? qe3.y : 0.f)
             + (sd3.z > 0.f ? qe3.z : 0.f) + (sd3.w > 0.f ? qe3.w : 0.f);

    // Warp reduce (3 scalars)
    #pragma unroll
    for (int off = 16; off > 0; off >>= 1) {
        diff2 += __shfl_down_sync(0xFFFFFFFFu, diff2, off);
        G2    += __shfl_down_sync(0xFFFFFFFFu, G2,    off);
        H2    += __shfl_down_sync(0xFFFFFFFFu, H2,    off);
    }

    // Block reduce via shared memory (4 warps per 128-thread block)
    __shared__ float sm[3][4];
    const int lane = threadIdx.x & 31;
    const int wid  = threadIdx.x >> 5;
    if (lane == 0) {
        sm[0][wid] = diff2; sm[1][wid] = G2; sm[2][wid] = H2;
    }
    __syncthreads();

    if (threadIdx.x == 0) {
        float v0 = 0.f, v1 = 0.f, v2 = 0.f;
        #pragma unroll
        for (int w = 0; w < 4; w++) {
            v0 += sm[0][w]; v1 += sm[1][w]; v2 += sm[2][w];
        }
        atomicAdd(&g_acc[0], (double)v0);
        atomicAdd(&g_acc[1], (double)v1);
        atomicAdd(&g_acc[2], (double)v2);

        // Order this block's accumulator atomics before the ticket.
        __threadfence();
        unsigned int old = atomicAdd(&g_count, 1u);
        if (old == (unsigned int)(GRID - 1)) {
            // Last block: all accumulator atomics are L2-visible.
            double diff2d = *((volatile double*)&g_acc[0]);
            double G2d    = *((volatile double*)&g_acc[1]);
            double H2d    = *((volatile double*)&g_acc[2]);
            out[0] = (float)(diff2d / G2d + LAMBDA * (diff2d / H2d));
            // Reset state for the next graph replay; no other thread-0 is
            // still touching these, and stream order protects later launches.
            *((volatile double*)&g_acc[0]) = 0.0;
            *((volatile double*)&g_acc[1]) = 0.0;
            *((volatile double*)&g_acc[2]) = 0.0;
            __threadfence();
            atomicExch(&g_count, 0u);
        }
    }
}

extern "C" void kernel_launch(void* const* d_in, const int* in_sizes, int n_in,
                              void* d_out, int out_size) {
    const float4* est = (const float4*)d_in[0];
    const float4* gt  = (const float4*)d_in[1];
    float* out = (float*)d_out;

    praloss_fused_kernel<<<GRID, TPB>>>(est, gt, out);
}